// round 16
// baseline (speedup 1.0000x reference)
#include <cuda_runtime.h>

#define HW    4096
#define BB    16
#define STEPS 409   // int(0.1 * 64 * 64)

typedef unsigned long long ull;
typedef unsigned int uint;

#define SENT 0xFFFFFFFFFFFFFFFFull
#define FINF __int_as_float(0x7F800000)
#define FNINF __int_as_float(0xFF800000)

// cross-CTA coordination (zeroed in-kernel via generation handshake)
__device__ uint d_mask[STEPS];   // per-step solved bitmask across batches
__device__ uint d_prog[BB];      // per-batch completed-step counter
__device__ uint d_ready;         // monotone generation counter across launches

__device__ __forceinline__ uint rmin(uint v){uint d;asm volatile("redux.sync.min.u32 %0, %1, 0xffffffff;":"=r"(d):"r"(v):"memory");return d;}

__device__ __forceinline__ ull packf(float f, int idx){
    return ((ull)__float_as_uint(f) << 32) | (ull)(uint)idx;
}
__device__ __forceinline__ ull umin64(ull a, ull b){ return a < b ? a : b; }
__device__ __forceinline__ uint umin32(uint a, uint b){ return a < b ? a : b; }

// ---- predicated ops (0-BSSY; ptxas won't emit these from C++ if{}) ----
__device__ __forceinline__ void stp_f32(bool p, uint a, float v){
    asm volatile("{.reg .pred q; setp.ne.u32 q,%0,0; @q st.shared.f32 [%1],%2;}"
        ::"r"((uint)p),"r"(a),"f"(v):"memory");
}
__device__ __forceinline__ void stp_u32(bool p, uint a, uint v){
    asm volatile("{.reg .pred q; setp.ne.u32 q,%0,0; @q st.shared.u32 [%1],%2;}"
        ::"r"((uint)p),"r"(a),"r"(v):"memory");
}
__device__ __forceinline__ void redp_or(bool p, uint* a, uint v){
    asm volatile("{.reg .pred q; setp.ne.u32 q,%0,0; @q red.global.or.b32 [%1],%2;}"
        ::"r"((uint)p),"l"(a),"r"(v):"memory");
}
__device__ __forceinline__ void stp_g_u32(bool p, uint* a, uint v){
    asm volatile("{.reg .pred q; setp.ne.u32 q,%0,0; @q st.volatile.global.u32 [%1],%2;}"
        ::"r"((uint)p),"l"(a),"r"(v):"memory");
}
__device__ __forceinline__ uint ldv_sh(uint a){
    uint v; asm volatile("ld.volatile.shared.u32 %0,[%1];":"=r"(v):"r"(a):"memory"); return v;
}

// ---- dynamic SMEM layout (bytes) ----
#define OFF_F      0        // float[4096]: f = 0.5(g+h+cost); +INF when not open
#define OFF_GV     16384    // float[4096]: +INF fresh-free / g open / -INF closed|obstacle
#define OFF_GC2    32768    // float[4096]: g+cost   (GV+GC2 overlaid by pm/hist/path later)
#define OFF_HC2    49152    // float[4096]: 0.5*(heuristic+cost)
#define OFF_COST   65536    // float[4096]: cost
#define OFF_ROWP   81920    // ull[64] per-row packed min (init handoff)
#define OFF_SELLOG 82432    // uint[512]
#define OFF_UPDCEL 84480    // uint[512*8] (0xFFFF sentinel = no update)
#define OFF_MISC   100864   // int[0]=goal, [1]=ts flag (0xFFFFFFFF=unset), [2]=step counter
#define SMEM_TOTAL 100880

__global__ void __launch_bounds__(512, 1)
astar_fused(const float* __restrict__ cost, const float* __restrict__ start,
            const float* __restrict__ goalm, const float* __restrict__ obst,
            float* __restrict__ out)
{
    extern __shared__ char smraw[];
    float*  s_f      = (float*)(smraw + OFF_F);
    float*  s_gv     = (float*)(smraw + OFF_GV);
    float*  s_gc2    = (float*)(smraw + OFF_GC2);
    float*  s_hc2    = (float*)(smraw + OFF_HC2);
    float*  s_cost   = (float*)(smraw + OFF_COST);
    ull*    s_rowp   = (ull*)(smraw + OFF_ROWP);
    uint*   s_sellog = (uint*)(smraw + OFF_SELLOG);
    uint*   s_updcel = (uint*)(smraw + OFF_UPDCEL);
    int*    s_misc   = (int*)(smraw + OFF_MISC);

    const int b    = blockIdx.x;
    const int tid  = threadIdx.x;
    const int lane = tid & 31;
    const int warp = tid >> 5;

    const float* cb = cost  + b * HW;
    const float* sb = start + b * HW;
    const float* gb = goalm + b * HW;
    const float* ob = obst  + b * HW;

    // ---- zero this CTA's slice of coordination state + find goal ----
    {
        int s = b + tid * BB;
        if (s < STEPS) d_mask[s] = 0u;
        if (tid == 0) { d_prog[b] = 0u; s_misc[1] = -1; s_misc[2] = 0; }
    }
    {   // vectorized goal scan (one-hot)
        const float4* g4 = (const float4*)gb;
        for (int c = tid; c < HW / 4; c += 512) {
            float4 v = g4[c];
            if (v.x > 0.5f) s_misc[0] = 4 * c + 0;
            if (v.y > 0.5f) s_misc[0] = 4 * c + 1;
            if (v.z > 0.5f) s_misc[0] = 4 * c + 2;
            if (v.w > 0.5f) s_misc[0] = 4 * c + 3;
        }
    }
    __threadfence();
    __syncthreads();
    if (tid == 0) {
        uint old = atomicAdd(&d_ready, 1u);
        uint target = ((old >> 4) + 1u) << 4;   // 16 CTAs per run-generation
        while (*((volatile uint*)&d_ready) < target) {}
        __threadfence();
    }
    __syncthreads();

    const int goalIdx = s_misc[0];
    const int grow = goalIdx >> 6, gcol = goalIdx & 63;

    // ---- per-cell init ----
    for (int c = tid; c < HW; c += 512) {
        int r = c >> 6, col = c & 63;
        int di = abs(r - grow), dj = abs(col - gcol);
        int cheb = (di > dj) ? di : dj;                 // sum - min = max
        float euc = sqrtf((float)(di * di + dj * dj));
        float h = __fadd_rn((float)cheb, __fmul_rn(0.001f, euc));
        float cc = cb[c];
        h = __fadd_rn(h, cc);                            // h_total = heuristic + cost
        float hc2 = __fmul_rn(0.5f, h);                  // exact halving
        s_hc2[c]  = hc2;
        s_cost[c] = cc;
        s_gc2[c]  = cc;                                  // g(0)+cost
        bool open = (sb[c] > 0.5f);
        bool free_ = (ob[c] > 0.5f);
        s_gv[c] = open ? 0.0f : (free_ ? FINF : FNINF);  // fresh=+INF, closed/obst=-INF
        s_f[c]  = open ? hc2 : FINF;                     // f = 0.5*0 + 0.5*h
    }
    __syncthreads();

    // ---- build per-row packed minima (16 warps x 4 rows) ----
    for (int k = 0; k < 4; k++) {
        int r = (warp << 2) + k, base = r << 6;
        ull q0 = packf(s_f[base + lane], base + lane);
        ull q1 = packf(s_f[base + 32 + lane], base + 32 + lane);
        ull q = umin64(q0, q1);
        uint hi = (uint)(q >> 32), M = rmin(hi);
        uint lo = (hi == M) ? (uint)q : 0xFFFFFFFFu, L = rmin(lo);
        if (lane == 0) s_rowp[r] = ((ull)M << 32) | L;
    }
    __syncthreads();

    const uint miscB = (uint)__cvta_generic_to_shared(s_misc);
    const uint slB   = (uint)__cvta_generic_to_shared(s_sellog);

    // ================= warp 0: pure A* driver (branchless body) =================
    if (warp == 0) {
        const bool lane0 = (lane == 0);
        const bool lane8 = (lane < 8);
        const uint fB  = (uint)__cvta_generic_to_shared(s_f);
        const uint gvB = (uint)__cvta_generic_to_shared(s_gv);
        const uint gcB = (uint)__cvta_generic_to_shared(s_gc2);
        const uint ueB = (uint)__cvta_generic_to_shared(s_updcel);

        // lane l owns rows l (rpA) and l+32 (rpB)
        ull rpA = s_rowp[lane], rpB = s_rowp[lane + 32];

        int step;
        for (step = 0; step < STEPS; ++step) {
            // stop-flag prefetch (consumed at loop bottom; latency hidden by body)
            uint fl = ldv_sh(miscB + 4u);

            // ---- global argmin from register row minima (tie: smallest idx) ----
            ull p = umin64(rpA, rpB);
            uint hi = (uint)(p >> 32);
            uint M = rmin(hi);
            uint lo = (hi == M) ? (uint)p : 0xFFFFFFFFu;
            uint L = rmin(lo);
            const int sel  = (int)(L & 0xFFFFu);
            const int srow = sel >> 6, scol = sel & 63, rb = srow << 6;
            const bool solved = (sel == goalIdx);

            float g2 = s_gc2[sel];                      // g[sel] + cost[sel]
            float k0 = s_f[rb + lane];                  // pre-update row snapshot
            float k1 = s_f[rb + 32 + lane];

            // ---- neighbor evaluation: all 32 lanes, one float compare ----
            int nidx = lane + (lane >= 4 ? 1 : 0);      // skip center (valid for lane<8)
            int ni = srow + nidx / 3 - 1;
            int nj = scol + nidx % 3 - 1;
            bool inb = lane8 & ((uint)ni < 64u) & ((uint)nj < 64u);
            int nbi = inb ? ((ni << 6) | nj) : sel;     // safe dummy index
            float gvN  = s_gv[nbi];   // +INF fresh / g open / -INF closed|obstacle
            float hc2N = s_hc2[nbi];
            float cN   = s_cost[nbi];
            bool upd  = inb & (gvN > g2);
            float nf  = __fmaf_rn(0.5f, g2, hc2N);      // 0.5*g2 + 0.5*(h+cost)
            ull npack = upd ? packf(nf, nbi) : SENT;

            // shfl_sync is the convergence point; validity rides in SENT.
            // pL/pR FIRST: they gate the removal rescan (critical path).
            ull pL = __shfl_sync(0xffffffffu, npack, 3);
            ull pR = __shfl_sync(0xffffffffu, npack, 4);

            // ---- removal rescan: 1 redux; column recovered by ballots ----
            ull p0 = packf(k0, rb + lane);
            ull p1 = packf(k1, rb + 32 + lane);
            p0 = ((scol < 32) & (lane == scol))        ? SENT : p0;
            p1 = ((scol >= 32) & (lane == scol - 32))  ? SENT : p1;
            {   // same-row substitutions (pL/pR are SENT when absent -> umin no-op)
                int cL = scol - 1, cR = scol + 1;
                p0 = ((cL >= 0) & (cL < 32) & (lane == cL))       ? umin64(p0, pL) : p0;
                p1 = ((cL >= 32) & (lane == cL - 32))             ? umin64(p1, pL) : p1;
                p0 = ((cR < 32) & (lane == cR))                   ? umin64(p0, pR) : p0;
                p1 = ((cR >= 32) & (cR < 64) & (lane == cR - 32)) ? umin64(p1, pR) : p1;
            }
            uint hi0 = (uint)(p0 >> 32), hi1 = (uint)(p1 >> 32);
            uint mm = rmin(umin32(hi0, hi1));
            uint balP0 = __ballot_sync(0xffffffffu, hi0 == mm);   // cols 0-31 first:
            uint balP1 = __ballot_sync(0xffffffffu, hi1 == mm);   // exact min-idx tie-break
            int rcol = balP0 ? (__ffs(balP0) - 1) : (32 + __ffs(balP1) - 1);
            ull newrow_uns = ((ull)mm << 32) | (uint)(rb + rcol);

            // remaining broadcasts overlap the rescan
            ull n0 = __shfl_sync(0xffffffffu, npack, 0);
            ull n1 = __shfl_sync(0xffffffffu, npack, 1);
            ull n2 = __shfl_sync(0xffffffffu, npack, 2);
            ull n5 = __shfl_sync(0xffffffffu, npack, 5);
            ull n6 = __shfl_sync(0xffffffffu, npack, 6);
            ull n7 = __shfl_sync(0xffffffffu, npack, 7);
            ull up1  = umin64(umin64(n0, n1), n2);      // row srow-1 decrease
            ull mid1 = umin64(pL, pR);                  // row srow   decrease
            ull dn1  = umin64(umin64(n5, n6), n7);      // row srow+1 decrease

            // ---- merge updated rows into register row minima (owner-lane local) ----
            {
                bool ownA = (srow < 32) & (lane == srow);
                bool ownB = (srow >= 32) & (lane == srow - 32);
                ull nrA = solved ? umin64(rpA, mid1) : newrow_uns;
                ull nrB = solved ? umin64(rpB, mid1) : newrow_uns;
                rpA = ownA ? nrA : rpA;
                rpB = ownB ? nrB : rpB;
            }
            {
                int rU = srow - 1, rD = srow + 1;
                rpA = ((rU >= 0) & (rU < 32) & (lane == rU))        ? umin64(rpA, up1) : rpA;
                rpB = ((rU >= 32) & (lane == rU - 32))              ? umin64(rpB, up1) : rpB;
                rpA = ((rD < 32) & (lane == rD))                    ? umin64(rpA, dn1) : rpA;
                rpB = ((rD >= 32) & (rD < 64) & (lane == rD - 32))  ? umin64(rpB, dn1) : rpB;
            }

            // ---- predicated SMEM writes (0-BSSY) ----
            stp_f32(upd, fB + (uint)nbi * 4u, nf);
            stp_f32(upd, gvB + (uint)nbi * 4u, g2);                  // open with g = g2
            stp_f32(upd, gcB + (uint)nbi * 4u, __fadd_rn(g2, cN));   // new g+cost
            stp_u32(lane8, ueB + (uint)(step * 8 + lane) * 4u, upd ? (uint)nbi : 0xFFFFu);

            stp_f32(lane0 & !solved, fB + (uint)sel * 4u, FINF);
            stp_f32(lane0 & !solved, gvB + (uint)sel * 4u, FNINF);   // close sel
            stp_u32(lane0, slB + (uint)step * 4u, (uint)sel);
            stp_u32(lane0, miscB + 8u, (uint)(step + 1));   // step counter (after sellog)

            if (fl != 0xFFFFFFFFu) { step++; break; }       // monitor says t_stop passed
        }
        // tell the monitor warp 0 is done (carries final step count)
        stp_u32(lane0, miscB + 8u, 0x80000000u | (uint)step);
    }
    // ================= warp 1: monitor (different SMSP than warp 0) =================
    else if (warp == 1) {
        const uint FULL = (1u << BB) - 1u;
        const bool lane0 = (lane == 0);
        int last = 0, tf = -1, scanpos = 0;
        uint pub = 0;
        while (true) {
            uint C = ldv_sh(miscB + 8u);
            uint sd = C & 0xFFFFu;
            if ((int)sd == last && tf < 0 && !(C & 0x80000000u)) {
                __nanosleep(100);               // throttle: cut SMEM-port contention
                continue;
            }
            // process newly completed steps: mask writes derived from sellog
            while (last < (int)sd) {
                uint sl = ldv_sh(slB + (uint)last * 4u);
                redp_or(lane0 & (sl == (uint)goalIdx), &d_mask[last], 1u << b);
                last++;
            }
            if (sd > pub) {                      // mask writes -> fence -> publish
                __threadfence();
                stp_g_u32(lane0, &d_prog[b], sd);
                pub = sd;
            }
            if (tf < 0) {
                uint pv = (lane < BB) ? *((volatile uint*)&d_prog[lane]) : 0xffffffffu;
                uint mn = rmin(pv);
                while (scanpos < (int)mn) {
                    int idx = scanpos + lane;
                    uint mv = (idx < (int)mn) ? *((volatile uint*)&d_mask[idx]) : 0u;
                    uint bal = __ballot_sync(0xffffffffu, mv == FULL);
                    if (bal) { tf = scanpos + __ffs(bal) - 1; break; }
                    scanpos += 32; if (scanpos > (int)mn) scanpos = (int)mn;
                }
                if (tf < 0 && scanpos >= STEPS) tf = STEPS - 1;   // never all-solved
            }
            if (tf >= 0) {
                stp_u32(lane0, miscB + 4u, (uint)tf);   // ts + stop flag for warp 0
                break;
            }
        }
    }
    __syncthreads();   // other 14 warps sleep here during the loop

    // ================= finalize (all 512 threads, SMEM logs) =================
    uint*          pm   = (uint*)(smraw + OFF_GV);               // overlay, 16KB
    unsigned char* hist = (unsigned char*)(smraw + OFF_GV + 16384);
    unsigned char* path = (unsigned char*)(smraw + OFF_GV + 20480);

    for (int c = tid; c < HW; c += 512) { pm[c] = 0u; hist[c] = 0; path[c] = 0; }
    __syncthreads();

    const int ts = s_misc[1];
    for (int s = tid; s <= ts; s += 512) {
        int sl = (int)s_sellog[s];
        hist[sl] = 1;
        uint packed = ((uint)(s + 1) << 12) | (uint)sl;          // last-writer wins
        #pragma unroll
        for (int k = 0; k < 8; k++) {
            uint ce = s_updcel[s * 8 + k];
            if (ce != 0xFFFFu) atomicMax(&pm[ce], packed);
        }
    }
    __syncthreads();

    if (tid == 0) {
        path[goalIdx] = 1;
        uint pv = pm[goalIdx];
        int loc = pv ? (int)(pv & 4095u) : goalIdx;
        for (int i = 0; i < ts; i++) {
            if (path[loc]) break;    // deterministic chase: revisit => future marks redundant
            path[loc] = 1;
            uint q = pm[loc];
            loc = q ? (int)(q & 4095u) : goalIdx;
        }
    }
    __syncthreads();

    for (int c = tid; c < HW; c += 512) {
        out[b * HW + c]           = hist[c] ? 1.0f : 0.0f;   // hist (B,1,64,64)
        out[BB * HW + b * HW + c] = path[c] ? 1.0f : 0.0f;   // path_maps (B,1,64,64)
    }
}

// ---------------- launch -------------------------------------------------
extern "C" void kernel_launch(void* const* d_in, const int* in_sizes, int n_in,
                              void* d_out, int out_size) {
    const float* cost  = (const float*)d_in[0];
    const float* start = (const float*)d_in[1];
    const float* goal  = (const float*)d_in[2];
    const float* obst  = (const float*)d_in[3];
    float* out = (float*)d_out;

    cudaFuncSetAttribute(astar_fused, cudaFuncAttributeMaxDynamicSharedMemorySize, SMEM_TOTAL);
    astar_fused<<<BB, 512, SMEM_TOTAL>>>(cost, start, goal, obst, out);
}

// round 17
// speedup vs baseline: 1.1173x; 1.1173x over previous
#include <cuda_runtime.h>

#define HW    4096
#define BB    16
#define STEPS 409   // int(0.1 * 64 * 64)

typedef unsigned long long ull;
typedef unsigned int uint;

#define SENT 0xFFFFFFFFFFFFFFFFull
#define FINF __int_as_float(0x7F800000)

// cross-CTA coordination (zeroed in-kernel via generation handshake)
__device__ uint d_mask[STEPS];   // per-step solved bitmask across batches
__device__ uint d_prog[BB];      // per-batch completed-step counter
__device__ uint d_ready;         // monotone generation counter across launches

__device__ __forceinline__ uint rmin(uint v){uint d;asm volatile("redux.sync.min.u32 %0, %1, 0xffffffff;":"=r"(d):"r"(v):"memory");return d;}

__device__ __forceinline__ ull packf(float f, int idx){
    return ((ull)__float_as_uint(f) << 32) | (ull)(uint)idx;
}
__device__ __forceinline__ ull umin64(ull a, ull b){ return a < b ? a : b; }

// ---- predicated ops (0-BSSY; ptxas won't emit these from C++ if{}) ----
__device__ __forceinline__ void stp_f32(bool p, uint a, float v){
    asm volatile("{.reg .pred q; setp.ne.u32 q,%0,0; @q st.shared.f32 [%1],%2;}"
        ::"r"((uint)p),"r"(a),"f"(v):"memory");
}
__device__ __forceinline__ void stp_u32(bool p, uint a, uint v){
    asm volatile("{.reg .pred q; setp.ne.u32 q,%0,0; @q st.shared.u32 [%1],%2;}"
        ::"r"((uint)p),"r"(a),"r"(v):"memory");
}
__device__ __forceinline__ void redp_or(bool p, uint* a, uint v){
    asm volatile("{.reg .pred q; setp.ne.u32 q,%0,0; @q red.global.or.b32 [%1],%2;}"
        ::"r"((uint)p),"l"(a),"r"(v):"memory");
}
__device__ __forceinline__ void stp_g_u32(bool p, uint* a, uint v){
    asm volatile("{.reg .pred q; setp.ne.u32 q,%0,0; @q st.volatile.global.u32 [%1],%2;}"
        ::"r"((uint)p),"l"(a),"r"(v):"memory");
}
__device__ __forceinline__ uint ldv_sh(uint a){
    uint v; asm volatile("ld.volatile.shared.u32 %0,[%1];":"=r"(v):"r"(a):"memory"); return v;
}

// ---- dynamic SMEM layout (bytes) ----
#define OFF_F      0        // float[4096]: f = 0.5(g+h+cost); +INF when not open
#define OFF_GPAIR  16384    // float2[4096] {g, cost}; overlaid by pm/hist/path in finalize
#define OFF_HC     49152    // float[4096] heuristic+cost
#define OFF_STATE  65536    // uint[4096] bit0 open, bit1 closed, bit2 free
#define OFF_ROWP   81920    // ull[64] per-row packed min (init handoff)
#define OFF_SELLOG 82432    // uint[512]
#define OFF_UPDCEL 86528    // uint[512*8] (0xFFFF sentinel = no update)
#define OFF_MISC   102912   // int[0]=goal, [1]=ts flag (0xFFFFFFFF=unset), [2]=step counter
#define SMEM_TOTAL 102928

__global__ void __launch_bounds__(512, 1)
astar_fused(const float* __restrict__ cost, const float* __restrict__ start,
            const float* __restrict__ goalm, const float* __restrict__ obst,
            float* __restrict__ out)
{
    extern __shared__ char smraw[];
    float*  s_f      = (float*)(smraw + OFF_F);
    float2* s_gp     = (float2*)(smraw + OFF_GPAIR);
    float*  s_hc     = (float*)(smraw + OFF_HC);
    uint*   s_state  = (uint*)(smraw + OFF_STATE);
    ull*    s_rowp   = (ull*)(smraw + OFF_ROWP);
    uint*   s_sellog = (uint*)(smraw + OFF_SELLOG);
    uint*   s_updcel = (uint*)(smraw + OFF_UPDCEL);
    int*    s_misc   = (int*)(smraw + OFF_MISC);

    const int b    = blockIdx.x;
    const int tid  = threadIdx.x;
    const int lane = tid & 31;
    const int warp = tid >> 5;

    const float* cb = cost  + b * HW;
    const float* sb = start + b * HW;
    const float* gb = goalm + b * HW;
    const float* ob = obst  + b * HW;

    // ---- zero this CTA's slice of coordination state + find goal ----
    {
        int s = b + tid * BB;
        if (s < STEPS) d_mask[s] = 0u;
        if (tid == 0) { d_prog[b] = 0u; s_misc[1] = -1; s_misc[2] = 0; }
    }
    {   // vectorized goal scan (one-hot)
        const float4* g4 = (const float4*)gb;
        for (int c = tid; c < HW / 4; c += 512) {
            float4 v = g4[c];
            if (v.x > 0.5f) s_misc[0] = 4 * c + 0;
            if (v.y > 0.5f) s_misc[0] = 4 * c + 1;
            if (v.z > 0.5f) s_misc[0] = 4 * c + 2;
            if (v.w > 0.5f) s_misc[0] = 4 * c + 3;
        }
    }
    __threadfence();
    __syncthreads();
    if (tid == 0) {
        uint old = atomicAdd(&d_ready, 1u);
        uint target = ((old >> 4) + 1u) << 4;   // 16 CTAs per run-generation
        while (*((volatile uint*)&d_ready) < target) {}
        __threadfence();
    }
    __syncthreads();

    const int goalIdx = s_misc[0];
    const int grow = goalIdx >> 6, gcol = goalIdx & 63;

    // ---- per-cell init ----
    for (int c = tid; c < HW; c += 512) {
        int r = c >> 6, col = c & 63;
        int di = abs(r - grow), dj = abs(col - gcol);
        int cheb = (di > dj) ? di : dj;                 // sum - min = max
        float euc = sqrtf((float)(di * di + dj * dj));
        float h = __fadd_rn((float)cheb, __fmul_rn(0.001f, euc));
        float cc = cb[c];
        h = __fadd_rn(h, cc);                            // h_total = heuristic + cost
        s_hc[c] = h;
        s_gp[c] = make_float2(0.0f, cc);
        uint st = 0;
        if (ob[c] > 0.5f) st |= 4u;
        bool open = (sb[c] > 0.5f);
        if (open) st |= 1u;
        s_state[c] = st;
        s_f[c] = open ? __fmul_rn(0.5f, h) : FINF;       // f = 0.5*0 + 0.5*h
    }
    __syncthreads();

    // ---- build per-row packed minima (16 warps x 4 rows) ----
    for (int k = 0; k < 4; k++) {
        int r = (warp << 2) + k, base = r << 6;
        ull q0 = packf(s_f[base + lane], base + lane);
        ull q1 = packf(s_f[base + 32 + lane], base + 32 + lane);
        ull q = umin64(q0, q1);
        uint hi = (uint)(q >> 32), M = rmin(hi);
        uint lo = (hi == M) ? (uint)q : 0xFFFFFFFFu, L = rmin(lo);
        if (lane == 0) s_rowp[r] = ((ull)M << 32) | L;
    }
    __syncthreads();

    const uint miscB = (uint)__cvta_generic_to_shared(s_misc);
    const uint slB   = (uint)__cvta_generic_to_shared(s_sellog);

    // ================= warp 0: pure A* driver (branchless body) =================
    if (warp == 0) {
        const bool lane0 = (lane == 0);
        const bool lane8 = (lane < 8);
        const uint fB  = (uint)__cvta_generic_to_shared(s_f);
        const uint gpB = (uint)__cvta_generic_to_shared(s_gp);
        const uint stB = (uint)__cvta_generic_to_shared(s_state);
        const uint ueB = (uint)__cvta_generic_to_shared(s_updcel);

        // lane l owns rows l (rpA) and l+32 (rpB)
        ull rpA = s_rowp[lane], rpB = s_rowp[lane + 32];

        int step;
        for (step = 0; step < STEPS; ++step) {
            // stop-flag prefetch (consumed at loop bottom; latency hidden by body)
            uint fl = ldv_sh(miscB + 4u);

            // ---- global argmin from register row minima (tie: smallest idx) ----
            ull p = umin64(rpA, rpB);
            uint hi = (uint)(p >> 32);
            uint M = rmin(hi);
            uint lo = (hi == M) ? (uint)p : 0xFFFFFFFFu;
            uint L = rmin(lo);
            const int sel  = (int)(L & 0xFFFFu);
            const int srow = sel >> 6, scol = sel & 63, rb = srow << 6;
            const bool solved = (sel == goalIdx);

            float2 gp = s_gp[sel];
            float g2 = __fadd_rn(gp.x, gp.y);           // g[sel] + cost[sel]
            float k0 = s_f[rb + lane];                  // pre-update row snapshot
            float k1 = s_f[rb + 32 + lane];

            // ---- neighbor evaluation: all 32 lanes, no branches ----
            int nidx = lane + (lane >= 4 ? 1 : 0);      // skip center (valid for lane<8)
            int ni = srow + nidx / 3 - 1;
            int nj = scol + nidx % 3 - 1;
            bool inb = lane8 & ((uint)ni < 64u) & ((uint)nj < 64u);
            int nbi = inb ? ((ni << 6) | nj) : sel;     // safe dummy index
            uint stN  = s_state[nbi];
            float gn  = s_gp[nbi].x;
            float hcN = s_hc[nbi];
            bool fre  = (stN & 4u) != 0u;
            bool opn  = (stN & 1u) != 0u;
            bool cls  = (stN & 2u) != 0u;
            bool upd  = inb & fre & ((!opn & !cls) | (opn & (gn > g2)));
            float nf  = __fmul_rn(0.5f, __fadd_rn(g2, hcN));   // 0.5*g2 + 0.5*h
            ull npack = upd ? packf(nf, nbi) : SENT;

            // shfl_sync is the convergence point; validity rides in SENT
            ull n0 = __shfl_sync(0xffffffffu, npack, 0);
            ull n1 = __shfl_sync(0xffffffffu, npack, 1);
            ull n2 = __shfl_sync(0xffffffffu, npack, 2);
            ull pL = __shfl_sync(0xffffffffu, npack, 3);
            ull pR = __shfl_sync(0xffffffffu, npack, 4);
            ull n5 = __shfl_sync(0xffffffffu, npack, 5);
            ull n6 = __shfl_sync(0xffffffffu, npack, 6);
            ull n7 = __shfl_sync(0xffffffffu, npack, 7);
            ull up1  = umin64(umin64(n0, n1), n2);      // row srow-1 decrease
            ull mid1 = umin64(pL, pR);                  // row srow   decrease
            ull dn1  = umin64(umin64(n5, n6), n7);      // row srow+1 decrease

            // ---- removal rescan (always executed; selected by `solved` later) ----
            ull p0 = packf(k0, rb + lane);
            ull p1 = packf(k1, rb + 32 + lane);
            p0 = ((scol < 32) & (lane == scol))        ? SENT : p0;
            p1 = ((scol >= 32) & (lane == scol - 32))  ? SENT : p1;
            {   // same-row substitutions (pL/pR are SENT when absent -> umin no-op)
                int cL = scol - 1, cR = scol + 1;
                p0 = ((cL >= 0) & (cL < 32) & (lane == cL))       ? umin64(p0, pL) : p0;
                p1 = ((cL >= 32) & (lane == cL - 32))             ? umin64(p1, pL) : p1;
                p0 = ((cR < 32) & (lane == cR))                   ? umin64(p0, pR) : p0;
                p1 = ((cR >= 32) & (cR < 64) & (lane == cR - 32)) ? umin64(p1, pR) : p1;
            }
            ull pp = umin64(p0, p1);
            uint h2 = (uint)(pp >> 32);
            uint mm = rmin(h2);
            uint l2 = (h2 == mm) ? (uint)pp : 0xFFFFFFFFu;
            uint lm2 = rmin(l2);
            ull newrow_uns = ((ull)mm << 32) | lm2;

            ull curA = __shfl_sync(0xffffffffu, rpA, srow & 31);
            ull curB = __shfl_sync(0xffffffffu, rpB, srow & 31);
            ull cur  = (srow < 32) ? curA : curB;
            ull newrow = solved ? umin64(cur, mid1) : newrow_uns;

            // ---- merge updated rows into register row minima (SELs) ----
            rpA = ((srow < 32) & (lane == srow))        ? newrow : rpA;
            rpB = ((srow >= 32) & (lane == srow - 32))  ? newrow : rpB;
            {
                int rU = srow - 1, rD = srow + 1;
                rpA = ((rU >= 0) & (rU < 32) & (lane == rU))        ? umin64(rpA, up1) : rpA;
                rpB = ((rU >= 32) & (lane == rU - 32))              ? umin64(rpB, up1) : rpB;
                rpA = ((rD < 32) & (lane == rD))                    ? umin64(rpA, dn1) : rpA;
                rpB = ((rD >= 32) & (rD < 64) & (lane == rD - 32))  ? umin64(rpB, dn1) : rpB;
            }

            // ---- predicated SMEM writes (0-BSSY) ----
            stp_f32(upd, fB + (uint)nbi * 4u, nf);
            stp_f32(upd, gpB + (uint)nbi * 8u, g2);
            stp_u32(upd, stB + (uint)nbi * 4u, stN | 1u);
            stp_u32(lane8, ueB + (uint)(step * 8 + lane) * 4u, upd ? (uint)nbi : 0xFFFFu);

            // sel was open => free bit set; new state is a constant
            stp_f32(lane0 & !solved, fB + (uint)sel * 4u, FINF);
            stp_u32(lane0, stB + (uint)sel * 4u, solved ? 7u : 6u);
            stp_u32(lane0, slB + (uint)step * 4u, (uint)sel);
            stp_u32(lane0, miscB + 8u, (uint)(step + 1));   // step counter (after sellog)

            if (fl != 0xFFFFFFFFu) { step++; break; }       // monitor says t_stop passed
        }
        // tell the monitor warp 0 is done (carries final step count)
        stp_u32(lane0, miscB + 8u, 0x80000000u | (uint)step);
    }
    // ================= warp 1: monitor (different SMSP than warp 0) =================
    else if (warp == 1) {
        const uint FULL = (1u << BB) - 1u;
        const bool lane0 = (lane == 0);
        int last = 0, tf = -1, scanpos = 0;
        uint pub = 0;
        while (true) {
            uint C = ldv_sh(miscB + 8u);
            uint sd = C & 0xFFFFu;
            // process newly completed steps: mask writes derived from sellog
            while (last < (int)sd) {
                uint sl = ldv_sh(slB + (uint)last * 4u);
                redp_or(lane0 & (sl == (uint)goalIdx), &d_mask[last], 1u << b);
                last++;
            }
            if (sd > pub) {                      // mask writes -> fence -> publish
                __threadfence();
                stp_g_u32(lane0, &d_prog[b], sd);
                pub = sd;
            }
            if (tf < 0) {
                uint pv = (lane < BB) ? *((volatile uint*)&d_prog[lane]) : 0xffffffffu;
                uint mn = rmin(pv);
                while (scanpos < (int)mn) {
                    int idx = scanpos + lane;
                    uint mv = (idx < (int)mn) ? *((volatile uint*)&d_mask[idx]) : 0u;
                    uint bal = __ballot_sync(0xffffffffu, mv == FULL);
                    if (bal) { tf = scanpos + __ffs(bal) - 1; break; }
                    scanpos += 32; if (scanpos > (int)mn) scanpos = (int)mn;
                }
                if (tf < 0 && scanpos >= STEPS) tf = STEPS - 1;   // never all-solved
            }
            if (tf >= 0) {
                stp_u32(lane0, miscB + 4u, (uint)tf);   // ts + stop flag for warp 0
                break;
            }
        }
    }
    __syncthreads();   // other 14 warps sleep here during the loop

    // ================= finalize (all 512 threads, SMEM logs) =================
    uint*          pm   = (uint*)(smraw + OFF_GPAIR);            // overlay, 16KB
    unsigned char* hist = (unsigned char*)(smraw + OFF_GPAIR + 16384);
    unsigned char* path = (unsigned char*)(smraw + OFF_GPAIR + 20480);

    for (int c = tid; c < HW; c += 512) { pm[c] = 0u; hist[c] = 0; path[c] = 0; }
    __syncthreads();

    const int ts = s_misc[1];
    for (int s = tid; s <= ts; s += 512) {
        int sl = (int)s_sellog[s];
        hist[sl] = 1;
        uint packed = ((uint)(s + 1) << 12) | (uint)sl;          // last-writer wins
        #pragma unroll
        for (int k = 0; k < 8; k++) {
            uint ce = s_updcel[s * 8 + k];
            if (ce != 0xFFFFu) atomicMax(&pm[ce], packed);
        }
    }
    __syncthreads();

    if (tid == 0) {
        path[goalIdx] = 1;
        uint pv = pm[goalIdx];
        int loc = pv ? (int)(pv & 4095u) : goalIdx;
        for (int i = 0; i < ts; i++) {
            if (path[loc]) break;    // deterministic chase: revisit => future marks redundant
            path[loc] = 1;
            uint q = pm[loc];
            loc = q ? (int)(q & 4095u) : goalIdx;
        }
    }
    __syncthreads();

    for (int c = tid; c < HW; c += 512) {
        out[b * HW + c]           = hist[c] ? 1.0f : 0.0f;   // hist (B,1,64,64)
        out[BB * HW + b * HW + c] = path[c] ? 1.0f : 0.0f;   // path_maps (B,1,64,64)
    }
}

// ---------------- launch -------------------------------------------------
extern "C" void kernel_launch(void* const* d_in, const int* in_sizes, int n_in,
                              void* d_out, int out_size) {
    const float* cost  = (const float*)d_in[0];
    const float* start = (const float*)d_in[1];
    const float* goal  = (const float*)d_in[2];
    const float* obst  = (const float*)d_in[3];
    float* out = (float*)d_out;

    cudaFuncSetAttribute(astar_fused, cudaFuncAttributeMaxDynamicSharedMemorySize, SMEM_TOTAL);
    astar_fused<<<BB, 512, SMEM_TOTAL>>>(cost, start, goal, obst, out);
}